// round 6
// baseline (speedup 1.0000x reference)
#include <cuda_runtime.h>
#include <math.h>
#include <stdint.h>
#include <stddef.h>

#define Bb 128
#define Ss 256
#define Ii 256
#define Hh 1024
#define Oo 256
#define NBLK 128

// ------------------------- device scratch (no allocations allowed) -------------
__device__ float g_xz[Ss * Bb];
__device__ float g_xr[Ss * Bb];
__device__ float g_xg[(size_t)Ss * Bb * Hh];   // 128 MB
__device__ float g_hs[(size_t)Ss * Bb * Hh];   // 128 MB
__device__ float g_ht[2][Hh * Bb];             // hidden state, k-major [k][b], dbl buf
__device__ unsigned g_bar_count;
__device__ volatile unsigned g_bar_gen;

// ------------------------- grid barrier (all NBLK CTAs resident) ---------------
__device__ __forceinline__ void grid_barrier() {
    __syncthreads();
    if (threadIdx.x == 0) {
        __threadfence();
        unsigned gen = g_bar_gen;
        unsigned t = atomicAdd(&g_bar_count, 1u);
        if (t == gridDim.x - 1) {
            g_bar_count = 0;
            __threadfence();
            g_bar_gen = gen + 1u;
        } else {
            while (g_bar_gen == gen) { __nanosleep(64); }
        }
        __threadfence();
    }
    __syncthreads();
}

// ------------------------- scalar-gate projections ----------------------------
// row r = s*Bb + b ; amode=1: A row at (b*Ss + s)*K (x is (B,S,I)); amode=0: row r*K
__global__ void __launch_bounds__(256) proj_zr(
    const float* __restrict__ A, const float* __restrict__ Wxz,
    const float* __restrict__ Wxr, const float* __restrict__ bxr,
    float* __restrict__ xz, float* __restrict__ xr, int K, int amode)
{
    int warp = blockIdx.x * (blockDim.x >> 5) + (threadIdx.x >> 5);
    int lane = threadIdx.x & 31;
    const float* row;
    if (amode) {
        int s = warp >> 7, b = warp & 127;
        row = A + ((size_t)b * Ss + s) * K;
    } else {
        row = A + (size_t)warp * K;
    }
    float az = 0.f, ar = 0.f;
    for (int k = lane; k < K; k += 32) {
        float v = row[k];
        az = fmaf(v, Wxz[k], az);
        ar = fmaf(v, Wxr[k], ar);
    }
#pragma unroll
    for (int d = 16; d; d >>= 1) {
        az += __shfl_down_sync(0xffffffffu, az, d);
        ar += __shfl_down_sync(0xffffffffu, ar, d);
    }
    if (lane == 0) { xz[warp] = az; xr[warp] = ar + bxr[0]; }
}

// ------------------------- SGEMM: C[r,n] = sum_k Arow(r)[k] * Bw[n,k] ----------
// 128x128 tile, K-step 8, 256 threads, 8x8 microtile. All dims divide exactly.
// EPI==0: C row-major (M x N). EPI==1: sigmoid(v + bias[n]) scattered to (B,S,N).
template <int EPI>
__global__ void __launch_bounds__(256) sgemm_nt(
    const float* __restrict__ A, const float* __restrict__ Bw,
    float* __restrict__ C, int N, int K, int amode,
    const float* __restrict__ bias)
{
    __shared__ float sA[8][132];
    __shared__ float sB[8][132];

    const int tid = threadIdx.x;
    const int m0 = blockIdx.x * 128;
    const int n0 = blockIdx.y * 128;
    const int tx = tid & 15, ty = tid >> 4;
    const int lr = tid >> 1;
    const int lq = (tid & 1) * 4;

    const float* aptr;
    {
        int arow = m0 + lr;
        if (amode) {
            int s = arow >> 7, b = arow & 127;
            aptr = A + ((size_t)b * Ss + s) * K;
        } else {
            aptr = A + (size_t)arow * K;
        }
    }
    const float* bptr = Bw + (size_t)(n0 + lr) * K;

    float acc[8][8];
#pragma unroll
    for (int i = 0; i < 8; i++)
#pragma unroll
        for (int j = 0; j < 8; j++) acc[i][j] = 0.f;

#pragma unroll 1
    for (int k0 = 0; k0 < K; k0 += 8) {
        float4 av = *(const float4*)(aptr + k0 + lq);
        float4 bv = *(const float4*)(bptr + k0 + lq);
        __syncthreads();
        sA[lq + 0][lr] = av.x; sA[lq + 1][lr] = av.y;
        sA[lq + 2][lr] = av.z; sA[lq + 3][lr] = av.w;
        sB[lq + 0][lr] = bv.x; sB[lq + 1][lr] = bv.y;
        sB[lq + 2][lr] = bv.z; sB[lq + 3][lr] = bv.w;
        __syncthreads();
#pragma unroll
        for (int k = 0; k < 8; k++) {
            const float4* sa4 = (const float4*)(&sA[k][0]);
            const float4* sb4 = (const float4*)(&sB[k][0]);
            float4 a0 = sa4[ty], a1 = sa4[16 + ty];
            float4 b0 = sb4[tx], b1 = sb4[16 + tx];
            float a[8] = {a0.x, a0.y, a0.z, a0.w, a1.x, a1.y, a1.z, a1.w};
            float b[8] = {b0.x, b0.y, b0.z, b0.w, b1.x, b1.y, b1.z, b1.w};
#pragma unroll
            for (int i = 0; i < 8; i++)
#pragma unroll
                for (int j = 0; j < 8; j++)
                    acc[i][j] = fmaf(a[i], b[j], acc[i][j]);
        }
    }

#pragma unroll
    for (int ai = 0; ai < 8; ai++) {
        int row = m0 + ((ai >> 2) * 64) + ty * 4 + (ai & 3);
#pragma unroll
        for (int half = 0; half < 2; half++) {
            int col = n0 + half * 64 + tx * 4;
            float4 v = make_float4(acc[ai][half * 4 + 0], acc[ai][half * 4 + 1],
                                   acc[ai][half * 4 + 2], acc[ai][half * 4 + 3]);
            if (EPI == 0) {
                *(float4*)&C[(size_t)row * N + col] = v;
            } else {
                int s = row >> 7, b = row & 127;
                float4 bs = *(const float4*)(bias + col);
                v.x = 1.f / (1.f + expf(-(v.x + bs.x)));
                v.y = 1.f / (1.f + expf(-(v.y + bs.y)));
                v.z = 1.f / (1.f + expf(-(v.z + bs.z)));
                v.w = 1.f / (1.f + expf(-(v.w + bs.w)));
                *(float4*)&C[((size_t)b * Ss + s) * N + col] = v;
            }
        }
    }
}

// ------------------------- persistent GRU scan (one launch per layer) ----------
// grid = 128 CTAs: bt=blk>>5 (4 batch tiles of 32), nt=blk&31 (32 j tiles of 32).
// Whg slice (32 x 1024) resident in smem for all steps; h k-major in L2 via
// ldcg/stcg. One grid barrier per step; z/r dots fused into the matvec k-loop.
#define SCAN_SMEM_FLOATS (32*Hh + Hh + Hh + 8*1152 + 256 + 256 + 32 + 32 + 32)
#define SCAN_SMEM_BYTES  (SCAN_SMEM_FLOATS * 4)

__global__ void __launch_bounds__(256) gru_scan(
    const float* __restrict__ xz, const float* __restrict__ xr,
    const float* __restrict__ xg,
    const float* __restrict__ Whz, const float* __restrict__ Whr,
    const float* __restrict__ Whg,
    const float* __restrict__ bhz, const float* __restrict__ bhg,
    const float* __restrict__ h0l,          // per-b stride 2*Hh
    float* __restrict__ hs, float* __restrict__ hTl)  // hTl per-b stride 2*Hh
{
    extern __shared__ float smem[];
    float* Wg   = smem;                  // [32][1024]
    float* swz  = Wg + 32 * Hh;          // [1024]
    float* swr  = swz + Hh;              // [1024]
    float* red  = swr + Hh;              // [8][32][36]
    float* zred = red + 8 * 1152;        // [8][32]
    float* rred = zred + 256;            // [8][32]
    float* zv   = rred + 256;            // [32]
    float* rv   = zv + 32;               // [32]
    float* bg   = rv + 32;               // [32]

    const int tid  = threadIdx.x;
    const int w    = tid >> 5, lane = tid & 31;
    const int bt   = blockIdx.x >> 5, nt = blockIdx.x & 31;
    const int b0   = bt * 32, j0 = nt * 32;

    for (int idx = tid; idx < 32 * Hh; idx += 256)
        Wg[idx] = Whg[(size_t)(j0 + (idx >> 10)) * Hh + (idx & 1023)];
    for (int idx = tid; idx < Hh; idx += 256) { swz[idx] = Whz[idx]; swr[idx] = Whr[idx]; }
    if (tid < 32) bg[tid] = bhg[j0 + tid];
    const float bz = bhz[0];

    // init h buffer 0 (k-major) from h0 slice
    for (int idx = blockIdx.x * 256 + tid; idx < Bb * Hh; idx += NBLK * 256) {
        int b = idx & 127, k = idx >> 7;
        g_ht[0][idx] = h0l[(size_t)b * (2 * Hh) + k];
    }
    grid_barrier();

    const int ju = tid >> 3;           // update-phase j (0..31)
    const int bq = (tid & 7) * 4;      // update-phase b quad (0,4,..,28)
    const int kbase = w * 128;
    const float4* Wg4 = (const float4*)Wg;
    int cur = 0;

#pragma unroll 1
    for (int s = 0; s < Ss; s++) {
        const float* ht_c = g_ht[cur];
        float* ht_n = g_ht[cur ^ 1];

        // prefetch update-phase operands (independent of this step's h)
        float4 ho = __ldcg((const float4*)(ht_c + (j0 + ju) * Bb + b0 + bq));
        float xgv[4];
#pragma unroll
        for (int i = 0; i < 4; i++)
            xgv[i] = xg[(size_t)(s * Bb + b0 + bq + i) * Hh + j0 + ju];

        // --- matvec partial: lane owns b=b0+lane, warp owns k in [kbase,kbase+128)
        float acc[32];
#pragma unroll
        for (int j = 0; j < 32; j++) acc[j] = 0.f;
        float zacc = 0.f, racc = 0.f;

        float h0v = __ldcg(ht_c + (kbase + 0) * Bb + b0 + lane);
        float h1v = __ldcg(ht_c + (kbase + 1) * Bb + b0 + lane);
        float h2v = __ldcg(ht_c + (kbase + 2) * Bb + b0 + lane);
        float h3v = __ldcg(ht_c + (kbase + 3) * Bb + b0 + lane);

#pragma unroll 4
        for (int q = 0; q < 32; q++) {
            float a0 = h0v, a1 = h1v, a2 = h2v, a3 = h3v;
            if (q < 31) {
                int kn = kbase + (q + 1) * 4;
                h0v = __ldcg(ht_c + (kn + 0) * Bb + b0 + lane);
                h1v = __ldcg(ht_c + (kn + 1) * Bb + b0 + lane);
                h2v = __ldcg(ht_c + (kn + 2) * Bb + b0 + lane);
                h3v = __ldcg(ht_c + (kn + 3) * Bb + b0 + lane);
            }
            int kq = (kbase >> 2) + q;
            float4 zq = ((const float4*)swz)[kq];
            float4 rq = ((const float4*)swr)[kq];
            zacc = fmaf(a0, zq.x, fmaf(a1, zq.y, fmaf(a2, zq.z, fmaf(a3, zq.w, zacc))));
            racc = fmaf(a0, rq.x, fmaf(a1, rq.y, fmaf(a2, rq.z, fmaf(a3, rq.w, racc))));
#pragma unroll
            for (int j = 0; j < 32; j++) {
                float4 wq = Wg4[j * 256 + kq];
                acc[j] = fmaf(a0, wq.x, fmaf(a1, wq.y, fmaf(a2, wq.z, fmaf(a3, wq.w, acc[j]))));
            }
        }

        // --- cross-warp reduction
        zred[w * 32 + lane] = zacc;
        rred[w * 32 + lane] = racc;
        {
            float* rw = red + w * 1152;
#pragma unroll
            for (int j = 0; j < 32; j++) rw[j * 36 + lane] = acc[j];
        }
        __syncthreads();
        if (tid < 32) {
            float zs = 0.f, rs = 0.f;
#pragma unroll
            for (int ww = 0; ww < 8; ww++) { zs += zred[ww * 32 + tid]; rs += rred[ww * 32 + tid]; }
            float zval = xz[s * Bb + b0 + tid] + zs + bz;
            float rval = xr[s * Bb + b0 + tid] + rs;
            zv[tid] = 1.f / (1.f + expf(-zval));
            rv[tid] = 1.f / (1.f + expf(-rval));
        }
        __syncthreads();

        float m0 = 0.f, m1 = 0.f, m2 = 0.f, m3 = 0.f;
#pragma unroll
        for (int ww = 0; ww < 8; ww++) {
            float4 p = *(const float4*)(red + ww * 1152 + ju * 36 + bq);
            m0 += p.x; m1 += p.y; m2 += p.z; m3 += p.w;
        }
        float mm[4] = {m0, m1, m2, m3};
        float hof[4] = {ho.x, ho.y, ho.z, ho.w};
        float hn[4];
#pragma unroll
        for (int i = 0; i < 4; i++) {
            int bb = b0 + bq + i;
            float g = tanhf(xgv[i] + rv[bq + i] * mm[i] + bg[ju]);
            float zz = zv[bq + i];
            float v = zz * hof[i] + (1.f - zz) * g;
            hn[i] = v;
            hs[(size_t)(s * Bb + bb) * Hh + j0 + ju] = v;
        }
        __stcg((float4*)(ht_n + (j0 + ju) * Bb + b0 + bq),
               make_float4(hn[0], hn[1], hn[2], hn[3]));
        cur ^= 1;
        grid_barrier();
    }

    // write final hidden state (B, 2, H) slice for this layer
    const float* ht_c = g_ht[cur];
#pragma unroll
    for (int i = 0; i < 4; i++)
        hTl[(size_t)(b0 + bq + i) * (2 * Hh) + j0 + ju] =
            __ldcg(ht_c + (j0 + ju) * Bb + b0 + bq + i);
}

// ------------------------- launcher -------------------------------------------
extern "C" void kernel_launch(void* const* d_in, const int* in_sizes, int n_in,
                              void* d_out, int out_size) {
    (void)in_sizes; (void)n_in; (void)out_size;

    const float* x    = (const float*)d_in[0];
    const float* h0   = (const float*)d_in[1];
    const float* Wxz0 = (const float*)d_in[2];
    const float* Whz0 = (const float*)d_in[3];
    const float* bhz0 = (const float*)d_in[4];
    const float* Wxr0 = (const float*)d_in[5];
    const float* bxr0 = (const float*)d_in[6];
    const float* Whr0 = (const float*)d_in[7];
    const float* Wxg0 = (const float*)d_in[8];
    const float* Whg0 = (const float*)d_in[9];
    const float* bhg0 = (const float*)d_in[10];
    const float* Wxz1 = (const float*)d_in[11];
    const float* Whz1 = (const float*)d_in[12];
    const float* bhz1 = (const float*)d_in[13];
    const float* Wxr1 = (const float*)d_in[14];
    const float* bxr1 = (const float*)d_in[15];
    const float* Whr1 = (const float*)d_in[16];
    const float* Wxg1 = (const float*)d_in[17];
    const float* Whg1 = (const float*)d_in[18];
    const float* bhg1 = (const float*)d_in[19];
    const float* Why  = (const float*)d_in[20];
    const float* bhy  = (const float*)d_in[21];

    float* out   = (float*)d_out;
    float* out_y = out;                                  // (B,S,O)
    float* out_h = out + (size_t)Bb * Ss * Oo;           // (B,2,H)

    float *xzp, *xrp, *xgp, *hsp;
    cudaGetSymbolAddress((void**)&xzp, g_xz);
    cudaGetSymbolAddress((void**)&xrp, g_xr);
    cudaGetSymbolAddress((void**)&xgp, g_xg);
    cudaGetSymbolAddress((void**)&hsp, g_hs);

    cudaFuncSetAttribute(gru_scan, cudaFuncAttributeMaxDynamicSharedMemorySize,
                         SCAN_SMEM_BYTES);

    const int M = Ss * Bb;                // 32768
    dim3 gemmBlk(256);
    dim3 gemmGridH(M / 128, Hh / 128);    // (256, 8)
    dim3 gemmGridO(M / 128, Oo / 128);    // (256, 2)
    int projBlocks = M / 8;               // 8 warps per block

    // ----- layer 0 -----
    proj_zr<<<projBlocks, 256>>>(x, Wxz0, Wxr0, bxr0, xzp, xrp, Ii, 1);
    sgemm_nt<0><<<gemmGridH, gemmBlk>>>(x, Wxg0, xgp, Hh, Ii, 1, nullptr);
    gru_scan<<<NBLK, 256, SCAN_SMEM_BYTES>>>(
        xzp, xrp, xgp, Whz0, Whr0, Whg0, bhz0, bhg0,
        h0 + 0 * Hh, hsp, out_h + 0 * Hh);

    // ----- layer 1 -----
    proj_zr<<<projBlocks, 256>>>(hsp, Wxz1, Wxr1, bxr1, xzp, xrp, Hh, 0);
    sgemm_nt<0><<<gemmGridH, gemmBlk>>>(hsp, Wxg1, xgp, Hh, Hh, 0, nullptr);
    gru_scan<<<NBLK, 256, SCAN_SMEM_BYTES>>>(
        xzp, xrp, xgp, Whz1, Whr1, Whg1, bhz1, bhg1,
        h0 + 1 * Hh, hsp, out_h + 1 * Hh);

    // ----- output head: sigmoid(hs1 @ Why^T + bhy) -> (B,S,O) -----
    sgemm_nt<1><<<gemmGridO, gemmBlk>>>(hsp, Why, out_y, Oo, Hh, 0, bhy);
}

// round 7
// speedup vs baseline: 1.0032x; 1.0032x over previous
#include <cuda_runtime.h>
#include <math.h>
#include <stdint.h>
#include <stddef.h>

#define Bb 128
#define Ss 256
#define Ii 256
#define Hh 1024
#define Oo 256
#define NBLK 128

// ------------------------- f32x2 packed-FMA helpers (sm_103a) -------------------
__device__ __forceinline__ unsigned long long pack2(float lo, float hi) {
    unsigned long long d;
    asm("mov.b64 %0, {%1, %2};" : "=l"(d) : "r"(__float_as_uint(lo)), "r"(__float_as_uint(hi)));
    return d;
}
__device__ __forceinline__ float2 unpack2(unsigned long long v) {
    unsigned int lo, hi;
    asm("mov.b64 {%0, %1}, %2;" : "=r"(lo), "=r"(hi) : "l"(v));
    return make_float2(__uint_as_float(lo), __uint_as_float(hi));
}
__device__ __forceinline__ unsigned long long ffma2(
    unsigned long long a, unsigned long long b, unsigned long long c) {
    unsigned long long d;
    asm("fma.rn.f32x2 %0, %1, %2, %3;" : "=l"(d) : "l"(a), "l"(b), "l"(c));
    return d;
}

// ------------------------- device scratch (no allocations allowed) -------------
__device__ float g_xz[Ss * Bb];
__device__ float g_xr[Ss * Bb];
__device__ float g_xg[(size_t)Ss * Bb * Hh];   // 128 MB
__device__ float g_hs[(size_t)Ss * Bb * Hh];   // 128 MB
__device__ float g_ht[2][Hh * Bb];             // hidden state, k-major [k][b], dbl buf
__device__ unsigned g_bar_count;
__device__ volatile unsigned g_bar_gen;

// ------------------------- grid barrier (all NBLK CTAs resident) ---------------
__device__ __forceinline__ void grid_barrier() {
    __syncthreads();
    if (threadIdx.x == 0) {
        __threadfence();
        unsigned gen = g_bar_gen;
        unsigned t = atomicAdd(&g_bar_count, 1u);
        if (t == gridDim.x - 1) {
            g_bar_count = 0;
            __threadfence();
            g_bar_gen = gen + 1u;
        } else {
            while (g_bar_gen == gen) { __nanosleep(32); }
        }
        __threadfence();
    }
    __syncthreads();
}

// ------------------------- scalar-gate projections ----------------------------
__global__ void __launch_bounds__(256) proj_zr(
    const float* __restrict__ A, const float* __restrict__ Wxz,
    const float* __restrict__ Wxr, const float* __restrict__ bxr,
    float* __restrict__ xz, float* __restrict__ xr, int K, int amode)
{
    int warp = blockIdx.x * (blockDim.x >> 5) + (threadIdx.x >> 5);
    int lane = threadIdx.x & 31;
    const float* row;
    if (amode) {
        int s = warp >> 7, b = warp & 127;
        row = A + ((size_t)b * Ss + s) * K;
    } else {
        row = A + (size_t)warp * K;
    }
    float az = 0.f, ar = 0.f;
    for (int k = lane; k < K; k += 32) {
        float v = row[k];
        az = fmaf(v, Wxz[k], az);
        ar = fmaf(v, Wxr[k], ar);
    }
#pragma unroll
    for (int d = 16; d; d >>= 1) {
        az += __shfl_down_sync(0xffffffffu, az, d);
        ar += __shfl_down_sync(0xffffffffu, ar, d);
    }
    if (lane == 0) { xz[warp] = az; xr[warp] = ar + bxr[0]; }
}

// ------------------------- SGEMM (f32x2): C[r,n] = sum_k Arow(r)[k]*Bw[n,k] ----
// 128x128 tile, K-step 8, 256 threads, 8x8 microtile via 8x(4 f32x2 pairs).
// EPI==0: C row-major. EPI==1: sigmoid(v + bias[n]) scattered to (B,S,N).
template <int EPI>
__global__ void __launch_bounds__(256) sgemm_nt(
    const float* __restrict__ A, const float* __restrict__ Bw,
    float* __restrict__ C, int N, int K, int amode,
    const float* __restrict__ bias)
{
    __shared__ float sA[8][132];   // row stride 528B = 33*16 -> 16B aligned rows
    __shared__ float sB[8][132];

    const int tid = threadIdx.x;
    const int m0 = blockIdx.x * 128;
    const int n0 = blockIdx.y * 128;
    const int tx = tid & 15, ty = tid >> 4;
    const int lr = tid >> 1;
    const int lq = (tid & 1) * 4;

    const float* aptr;
    {
        int arow = m0 + lr;
        if (amode) {
            int s = arow >> 7, b = arow & 127;
            aptr = A + ((size_t)b * Ss + s) * K;
        } else {
            aptr = A + (size_t)arow * K;
        }
    }
    const float* bptr = Bw + (size_t)(n0 + lr) * K;

    unsigned long long acc2[8][4];
#pragma unroll
    for (int i = 0; i < 8; i++)
#pragma unroll
        for (int j = 0; j < 4; j++) acc2[i][j] = 0ull;

    float4 av = *(const float4*)(aptr + lq);
    float4 bv = *(const float4*)(bptr + lq);

#pragma unroll 1
    for (int k0 = 0; k0 < K; k0 += 8) {
        __syncthreads();
        sA[lq + 0][lr] = av.x; sA[lq + 1][lr] = av.y;
        sA[lq + 2][lr] = av.z; sA[lq + 3][lr] = av.w;
        sB[lq + 0][lr] = bv.x; sB[lq + 1][lr] = bv.y;
        sB[lq + 2][lr] = bv.z; sB[lq + 3][lr] = bv.w;
        __syncthreads();
        if (k0 + 8 < K) {           // prefetch next slab behind compute
            av = *(const float4*)(aptr + k0 + 8 + lq);
            bv = *(const float4*)(bptr + k0 + 8 + lq);
        }
#pragma unroll
        for (int k = 0; k < 8; k++) {
            const float4* sa4 = (const float4*)(&sA[k][0]);
            const ulonglong2* sb2 = (const ulonglong2*)(&sB[k][0]);
            float4 a0 = sa4[ty], a1 = sa4[16 + ty];
            ulonglong2 b0 = sb2[tx], b1 = sb2[16 + tx];
            unsigned long long ap[8];
            ap[0] = pack2(a0.x, a0.x); ap[1] = pack2(a0.y, a0.y);
            ap[2] = pack2(a0.z, a0.z); ap[3] = pack2(a0.w, a0.w);
            ap[4] = pack2(a1.x, a1.x); ap[5] = pack2(a1.y, a1.y);
            ap[6] = pack2(a1.z, a1.z); ap[7] = pack2(a1.w, a1.w);
#pragma unroll
            for (int i = 0; i < 8; i++) {
                acc2[i][0] = ffma2(ap[i], b0.x, acc2[i][0]);
                acc2[i][1] = ffma2(ap[i], b0.y, acc2[i][1]);
                acc2[i][2] = ffma2(ap[i], b1.x, acc2[i][2]);
                acc2[i][3] = ffma2(ap[i], b1.y, acc2[i][3]);
            }
        }
    }

#pragma unroll
    for (int ai = 0; ai < 8; ai++) {
        int row = m0 + ((ai >> 2) * 64) + ty * 4 + (ai & 3);
#pragma unroll
        for (int half = 0; half < 2; half++) {
            int col = n0 + half * 64 + tx * 4;
            float2 p0 = unpack2(acc2[ai][half * 2 + 0]);
            float2 p1 = unpack2(acc2[ai][half * 2 + 1]);
            float4 v = make_float4(p0.x, p0.y, p1.x, p1.y);
            if (EPI == 0) {
                *(float4*)&C[(size_t)row * N + col] = v;
            } else {
                int s = row >> 7, b = row & 127;
                float4 bs = *(const float4*)(bias + col);
                v.x = 1.f / (1.f + expf(-(v.x + bs.x)));
                v.y = 1.f / (1.f + expf(-(v.y + bs.y)));
                v.z = 1.f / (1.f + expf(-(v.z + bs.z)));
                v.w = 1.f / (1.f + expf(-(v.w + bs.w)));
                *(float4*)&C[((size_t)b * Ss + s) * N + col] = v;
            }
        }
    }
}

// ------------------------- persistent GRU scan (one launch per layer) ----------
#define SCAN_SMEM_FLOATS (32*Hh + Hh + Hh + 8*1152 + 256 + 256 + 32 + 32 + 32)
#define SCAN_SMEM_BYTES  (SCAN_SMEM_FLOATS * 4)

__global__ void __launch_bounds__(256) gru_scan(
    const float* __restrict__ xz, const float* __restrict__ xr,
    const float* __restrict__ xg,
    const float* __restrict__ Whz, const float* __restrict__ Whr,
    const float* __restrict__ Whg,
    const float* __restrict__ bhz, const float* __restrict__ bhg,
    const float* __restrict__ h0l,
    float* __restrict__ hs, float* __restrict__ hTl)
{
    extern __shared__ float smem[];
    float* Wg   = smem;                  // [32][1024]
    float* swz  = Wg + 32 * Hh;          // [1024]
    float* swr  = swz + Hh;              // [1024]
    float* red  = swr + Hh;              // [8][32][36]
    float* zred = red + 8 * 1152;        // [8][32]
    float* rred = zred + 256;            // [8][32]
    float* zv   = rred + 256;            // [32]
    float* rv   = zv + 32;               // [32]
    float* bg   = rv + 32;               // [32]

    const int tid  = threadIdx.x;
    const int w    = tid >> 5, lane = tid & 31;
    const int bt   = blockIdx.x >> 5, nt = blockIdx.x & 31;
    const int b0   = bt * 32, j0 = nt * 32;

    for (int idx = tid; idx < 32 * Hh; idx += 256)
        Wg[idx] = Whg[(size_t)(j0 + (idx >> 10)) * Hh + (idx & 1023)];
    for (int idx = tid; idx < Hh; idx += 256) { swz[idx] = Whz[idx]; swr[idx] = Whr[idx]; }
    if (tid < 32) bg[tid] = bhg[j0 + tid];
    const float bz = bhz[0];

    for (int idx = blockIdx.x * 256 + tid; idx < Bb * Hh; idx += NBLK * 256) {
        int b = idx & 127, k = idx >> 7;
        g_ht[0][idx] = h0l[(size_t)b * (2 * Hh) + k];
    }
    grid_barrier();

    const int ju = tid >> 3;
    const int bq = (tid & 7) * 4;
    const int kbase = w * 128;
    const ulonglong2* Wg2 = (const ulonglong2*)Wg;
    const ulonglong2* z2  = (const ulonglong2*)swz;
    const ulonglong2* r2  = (const ulonglong2*)swr;
    int cur = 0;

#pragma unroll 1
    for (int s = 0; s < Ss; s++) {
        const float* ht_c = g_ht[cur];
        float* ht_n = g_ht[cur ^ 1];

        float4 ho = __ldcg((const float4*)(ht_c + (j0 + ju) * Bb + b0 + bq));
        float xgv[4];
#pragma unroll
        for (int i = 0; i < 4; i++)
            xgv[i] = xg[(size_t)(s * Bb + b0 + bq + i) * Hh + j0 + ju];

        // --- matvec partial: lane owns b=b0+lane, warp owns k in [kbase,kbase+128)
        unsigned long long accP[32];
#pragma unroll
        for (int j = 0; j < 32; j++) accP[j] = 0ull;
        unsigned long long zaccP = 0ull, raccP = 0ull;

        float h0v = __ldcg(ht_c + (kbase + 0) * Bb + b0 + lane);
        float h1v = __ldcg(ht_c + (kbase + 1) * Bb + b0 + lane);
        float h2v = __ldcg(ht_c + (kbase + 2) * Bb + b0 + lane);
        float h3v = __ldcg(ht_c + (kbase + 3) * Bb + b0 + lane);

#pragma unroll 4
        for (int q = 0; q < 32; q++) {
            unsigned long long a01 = pack2(h0v, h1v);
            unsigned long long a23 = pack2(h2v, h3v);
            if (q < 31) {
                int kn = kbase + (q + 1) * 4;
                h0v = __ldcg(ht_c + (kn + 0) * Bb + b0 + lane);
                h1v = __ldcg(ht_c + (kn + 1) * Bb + b0 + lane);
                h2v = __ldcg(ht_c + (kn + 2) * Bb + b0 + lane);
                h3v = __ldcg(ht_c + (kn + 3) * Bb + b0 + lane);
            }
            int kq = (kbase >> 2) + q;
            ulonglong2 zq = z2[kq];
            ulonglong2 rq = r2[kq];
            zaccP = ffma2(a01, zq.x, ffma2(a23, zq.y, zaccP));
            raccP = ffma2(a01, rq.x, ffma2(a23, rq.y, raccP));
#pragma unroll
            for (int j = 0; j < 32; j++) {
                ulonglong2 wq = Wg2[j * 256 + kq];
                accP[j] = ffma2(a01, wq.x, ffma2(a23, wq.y, accP[j]));
            }
        }

        // --- cross-warp reduction
        {
            float2 zp = unpack2(zaccP), rp = unpack2(raccP);
            zred[w * 32 + lane] = zp.x + zp.y;
            rred[w * 32 + lane] = rp.x + rp.y;
            float* rw = red + w * 1152;
#pragma unroll
            for (int j = 0; j < 32; j++) {
                float2 p = unpack2(accP[j]);
                rw[j * 36 + lane] = p.x + p.y;
            }
        }
        __syncthreads();
        if (tid < 32) {
            float zs = 0.f, rs = 0.f;
#pragma unroll
            for (int ww = 0; ww < 8; ww++) { zs += zred[ww * 32 + tid]; rs += rred[ww * 32 + tid]; }
            float zval = xz[s * Bb + b0 + tid] + zs + bz;
            float rval = xr[s * Bb + b0 + tid] + rs;
            zv[tid] = 1.f / (1.f + expf(-zval));
            rv[tid] = 1.f / (1.f + expf(-rval));
        }
        __syncthreads();

        float m0 = 0.f, m1 = 0.f, m2 = 0.f, m3 = 0.f;
#pragma unroll
        for (int ww = 0; ww < 8; ww++) {
            float4 p = *(const float4*)(red + ww * 1152 + ju * 36 + bq);
            m0 += p.x; m1 += p.y; m2 += p.z; m3 += p.w;
        }
        float mm[4] = {m0, m1, m2, m3};
        float hof[4] = {ho.x, ho.y, ho.z, ho.w};
        float hn[4];
#pragma unroll
        for (int i = 0; i < 4; i++) {
            int bb = b0 + bq + i;
            float g = tanhf(xgv[i] + rv[bq + i] * mm[i] + bg[ju]);
            float zz = zv[bq + i];
            float v = zz * hof[i] + (1.f - zz) * g;
            hn[i] = v;
            hs[(size_t)(s * Bb + bb) * Hh + j0 + ju] = v;
        }
        __stcg((float4*)(ht_n + (j0 + ju) * Bb + b0 + bq),
               make_float4(hn[0], hn[1], hn[2], hn[3]));
        cur ^= 1;
        grid_barrier();
    }

    const float* ht_c = g_ht[cur];
#pragma unroll
    for (int i = 0; i < 4; i++)
        hTl[(size_t)(b0 + bq + i) * (2 * Hh) + j0 + ju] =
            __ldcg(ht_c + (j0 + ju) * Bb + b0 + bq + i);
}

// ------------------------- launcher -------------------------------------------
extern "C" void kernel_launch(void* const* d_in, const int* in_sizes, int n_in,
                              void* d_out, int out_size) {
    (void)in_sizes; (void)n_in; (void)out_size;

    const float* x    = (const float*)d_in[0];
    const float* h0   = (const float*)d_in[1];
    const float* Wxz0 = (const float*)d_in[2];
    const float* Whz0 = (const float*)d_in[3];
    const float* bhz0 = (const float*)d_in[4];
    const float* Wxr0 = (const float*)d_in[5];
    const float* bxr0 = (const float*)d_in[6];
    const float* Whr0 = (const float*)d_in[7];
    const float* Wxg0 = (const float*)d_in[8];
    const float* Whg0 = (const float*)d_in[9];
    const float* bhg0 = (const float*)d_in[10];
    const float* Wxz1 = (const float*)d_in[11];
    const float* Whz1 = (const float*)d_in[12];
    const float* bhz1 = (const float*)d_in[13];
    const float* Wxr1 = (const float*)d_in[14];
    const float* bxr1 = (const float*)d_in[15];
    const float* Whr1 = (const float*)d_in[16];
    const float* Wxg1 = (const float*)d_in[17];
    const float* Whg1 = (const float*)d_in[18];
    const float* bhg1 = (const float*)d_in[19];
    const float* Why  = (const float*)d_in[20];
    const float* bhy  = (const float*)d_in[21];

    float* out   = (float*)d_out;
    float* out_y = out;                                  // (B,S,O)
    float* out_h = out + (size_t)Bb * Ss * Oo;           // (B,2,H)

    float *xzp, *xrp, *xgp, *hsp;
    cudaGetSymbolAddress((void**)&xzp, g_xz);
    cudaGetSymbolAddress((void**)&xrp, g_xr);
    cudaGetSymbolAddress((void**)&xgp, g_xg);
    cudaGetSymbolAddress((void**)&hsp, g_hs);

    cudaFuncSetAttribute(gru_scan, cudaFuncAttributeMaxDynamicSharedMemorySize,
                         SCAN_SMEM_BYTES);

    const int M = Ss * Bb;                // 32768
    dim3 gemmBlk(256);
    dim3 gemmGridH(M / 128, Hh / 128);    // (256, 8)
    dim3 gemmGridO(M / 128, Oo / 128);    // (256, 2)
    int projBlocks = M / 8;

    // ----- layer 0 -----
    proj_zr<<<projBlocks, 256>>>(x, Wxz0, Wxr0, bxr0, xzp, xrp, Ii, 1);
    sgemm_nt<0><<<gemmGridH, gemmBlk>>>(x, Wxg0, xgp, Hh, Ii, 1, nullptr);
    gru_scan<<<NBLK, 256, SCAN_SMEM_BYTES>>>(
        xzp, xrp, xgp, Whz0, Whr0, Whg0, bhz0, bhg0,
        h0 + 0 * Hh, hsp, out_h + 0 * Hh);

    // ----- layer 1 -----
    proj_zr<<<projBlocks, 256>>>(hsp, Wxz1, Wxr1, bxr1, xzp, xrp, Hh, 0);
    sgemm_nt<0><<<gemmGridH, gemmBlk>>>(hsp, Wxg1, xgp, Hh, Hh, 0, nullptr);
    gru_scan<<<NBLK, 256, SCAN_SMEM_BYTES>>>(
        xzp, xrp, xgp, Whz1, Whr1, Whg1, bhz1, bhg1,
        h0 + 1 * Hh, hsp, out_h + 1 * Hh);

    // ----- output head: sigmoid(hs1 @ Why^T + bhy) -> (B,S,O) -----
    sgemm_nt<1><<<gemmGridO, gemmBlk>>>(hsp, Why, out_y, Oo, Hh, 0, bhy);
}